// round 2
// baseline (speedup 1.0000x reference)
#include <cuda_runtime.h>
#include <cstdint>

// Problem sizes
// B=16, T=512, E=256, H=256, HEADS=8, NL=3, NC=10
#define NBQ 128   // scan grid size (must be <= #SMs for co-residency)

// ---------------- scratch (static device memory; no allocations) -------------
__device__ __align__(16) float g_M[16*512*512];     // mixed adjacency (B,T,T)
__device__ __align__(16) float g_cat[8192*512];     // [Hemb | weighted] (B*T, 2E)
__device__ __align__(16) float g_c1[8192*256];
__device__ __align__(16) float g_c2[8192*256];
__device__ __align__(16) float g_next[8192*256];    // GRU input
__device__ __align__(16) float g_xg[8192*768];      // next_in @ W_ih^T + b_ih
__device__ __align__(16) float g_out[8192*256];     // GRU outputs (B,T,H)
__device__ __align__(16) float g_u[8192*256];       // tanh(outputs@W1^T+b1)
__device__ __align__(16) float g_a[8192*8];         // attention logits (B,T,HEADS)
__device__ __align__(16) float g_h[2][16*256];      // ping-pong hidden state
__device__ unsigned g_bar;                           // global barrier counter

// ---------------- barrier primitives ----------------------------------------
__device__ __forceinline__ void red_release(unsigned* p, unsigned v) {
    asm volatile("red.release.gpu.global.add.u32 [%0], %1;" :: "l"(p), "r"(v) : "memory");
}
__device__ __forceinline__ unsigned ld_acq(unsigned* p) {
    unsigned v;
    asm volatile("ld.acquire.gpu.global.u32 %0, [%1];" : "=r"(v) : "l"(p) : "memory");
    return v;
}

// ---------------- 1. embedding gather (also resets barrier) ------------------
// writes Hemb into left half of g_cat
__global__ void embed_kernel(const int* __restrict__ x, const float* __restrict__ emb) {
    if (blockIdx.x == 0 && threadIdx.x == 0) g_bar = 0u;
    int m = blockIdx.x;                       // 0..8191  (b*T + t)
    int tok = x[m];
    float4 v = *(const float4*)(emb + (size_t)tok * 256 + threadIdx.x * 4);
    *(float4*)(g_cat + (size_t)m * 512 + threadIdx.x * 4) = v;
}

// ---------------- 2. M = sum_l w_l*G + (1-w_l)*G_prod ------------------------
__global__ void mix_kernel(const float* __restrict__ G, const float* __restrict__ Gp,
                           const float* __restrict__ mw) {
    int i = blockIdx.x * blockDim.x + threadIdx.x;   // over 16*65536 float4s
    float w0 = mw[0], w1 = mw[1], w2 = mw[2];
    int b = i >> 16;
    int r = i & 65535;
    const float4* G4  = (const float4*)G;
    const float4* Gp4 = (const float4*)Gp;
    size_t base = (size_t)b * 3 * 65536 + r;
    float4 g0 = G4[base],           p0 = Gp4[base];
    float4 g1 = G4[base + 65536],   p1 = Gp4[base + 65536];
    float4 g2 = G4[base + 131072],  p2 = Gp4[base + 131072];
    float4 o;
    o.x = w0*g0.x + (1.f-w0)*p0.x + w1*g1.x + (1.f-w1)*p1.x + w2*g2.x + (1.f-w2)*p2.x;
    o.y = w0*g0.y + (1.f-w0)*p0.y + w1*g1.y + (1.f-w1)*p1.y + w2*g2.y + (1.f-w2)*p2.y;
    o.z = w0*g0.z + (1.f-w0)*p0.z + w1*g1.z + (1.f-w1)*p1.z + w2*g2.z + (1.f-w2)*p2.z;
    o.w = w0*g0.w + (1.f-w0)*p0.w + w1*g1.w + (1.f-w1)*p1.w + w2*g2.w + (1.f-w2)*p2.w;
    ((float4*)g_M)[i] = o;
}

// ---------------- 3. weighted = M^T @ Hemb  (TN GEMM, per batch) -------------
// C[i,d] = sum_j M[b][j][i] * cat[b*T+j][d]   -> written to cat cols 256..511
__global__ void __launch_bounds__(256) gemm_tn_kernel() {
    int bb = blockIdx.z;
    const float* A  = g_M   + (size_t)bb * 512 * 512;   // [j][i], ld 512
    const float* Bp = g_cat + (size_t)bb * 512 * 512;   // [j][d], ld 512 (cols 0..255)
    float* C        = g_cat + (size_t)bb * 512 * 512 + 256;  // [i][d], ld 512
    __shared__ __align__(16) float As[16][68];
    __shared__ __align__(16) float Bs[16][68];
    int i0 = blockIdx.x * 64, d0 = blockIdx.y * 64;
    int tid = threadIdx.x;
    int lr = tid >> 4;           // j within tile (0..15)
    int lc = (tid & 15) * 4;     // col within tile
    int m0 = (tid >> 4) * 4, n0 = (tid & 15) * 4;
    float acc[4][4];
#pragma unroll
    for (int a = 0; a < 4; ++a)
#pragma unroll
        for (int c = 0; c < 4; ++c) acc[a][c] = 0.f;
    for (int j0 = 0; j0 < 512; j0 += 16) {
        float4 av = *(const float4*)(A  + (size_t)(j0 + lr) * 512 + i0 + lc);
        float4 bv = *(const float4*)(Bp + (size_t)(j0 + lr) * 512 + d0 + lc);
        __syncthreads();
        *(float4*)&As[lr][lc] = av;
        *(float4*)&Bs[lr][lc] = bv;
        __syncthreads();
#pragma unroll
        for (int kk = 0; kk < 16; ++kk) {
            float a4[4], b4[4];
            *(float4*)a4 = *(const float4*)&As[kk][m0];
            *(float4*)b4 = *(const float4*)&Bs[kk][n0];
#pragma unroll
            for (int ii = 0; ii < 4; ++ii)
#pragma unroll
                for (int jj = 0; jj < 4; ++jj)
                    acc[ii][jj] = fmaf(a4[ii], b4[jj], acc[ii][jj]);
        }
    }
#pragma unroll
    for (int ii = 0; ii < 4; ++ii)
#pragma unroll
        for (int jj = 0; jj < 4; ++jj)
            C[(size_t)(i0 + m0 + ii) * 512 + d0 + n0 + jj] = acc[ii][jj];
}

// ---------------- generic NT GEMM: C[m,n] = sum_k A[m,k]*B[n,k] --------------
// mode: 0 = plain, 1 = +bias, 2 = tanh(+bias)
__global__ void __launch_bounds__(256) gemm_nt_kernel(const float* __restrict__ A,
                                                      const float* __restrict__ Bm,
                                                      float* __restrict__ C,
                                                      int N, int K,
                                                      const float* __restrict__ bias,
                                                      int mode) {
    __shared__ __align__(16) float As[16][68];
    __shared__ __align__(16) float Bs[16][68];
    int m0b = blockIdx.x * 64, n0b = blockIdx.y * 64;
    int tid = threadIdx.x;
    int lr = tid >> 2;          // row within 64-tile
    int lk = (tid & 3) * 4;     // k chunk
    int m0 = (tid >> 4) * 4, n0 = (tid & 15) * 4;
    float acc[4][4];
#pragma unroll
    for (int a = 0; a < 4; ++a)
#pragma unroll
        for (int c = 0; c < 4; ++c) acc[a][c] = 0.f;
    for (int k0 = 0; k0 < K; k0 += 16) {
        float4 av = *(const float4*)(A  + (size_t)(m0b + lr) * K + k0 + lk);
        float4 bv = *(const float4*)(Bm + (size_t)(n0b + lr) * K + k0 + lk);
        __syncthreads();
        As[lk+0][lr] = av.x; As[lk+1][lr] = av.y; As[lk+2][lr] = av.z; As[lk+3][lr] = av.w;
        Bs[lk+0][lr] = bv.x; Bs[lk+1][lr] = bv.y; Bs[lk+2][lr] = bv.z; Bs[lk+3][lr] = bv.w;
        __syncthreads();
#pragma unroll
        for (int kk = 0; kk < 16; ++kk) {
            float a4[4], b4[4];
            *(float4*)a4 = *(const float4*)&As[kk][m0];
            *(float4*)b4 = *(const float4*)&Bs[kk][n0];
#pragma unroll
            for (int ii = 0; ii < 4; ++ii)
#pragma unroll
                for (int jj = 0; jj < 4; ++jj)
                    acc[ii][jj] = fmaf(a4[ii], b4[jj], acc[ii][jj]);
        }
    }
#pragma unroll
    for (int ii = 0; ii < 4; ++ii)
#pragma unroll
        for (int jj = 0; jj < 4; ++jj) {
            float v = acc[ii][jj];
            if (mode >= 1) v += bias[n0b + n0 + jj];
            if (mode == 2) v = tanhf(v);
            C[(size_t)(m0b + m0 + ii) * N + n0b + n0 + jj] = v;
        }
}

// ---------------- 5. GLU combine: next = c1 * sigmoid(c2) --------------------
__global__ void glu_kernel() {
    int i = blockIdx.x * blockDim.x + threadIdx.x;    // over 8192*256/4 float4s
    float4 a = ((const float4*)g_c1)[i];
    float4 b = ((const float4*)g_c2)[i];
    float4 o;
    o.x = a.x / (1.f + __expf(-b.x));
    o.y = a.y / (1.f + __expf(-b.y));
    o.z = a.z / (1.f + __expf(-b.z));
    o.w = a.w / (1.f + __expf(-b.w));
    ((float4*)g_next)[i] = o;
}

// ---------------- 7. persistent GRU scan -------------------------------------
// 128 blocks x 256 threads, all co-resident. Block bx owns hidden cols
// j in {2*bx, 2*bx+1} for ALL 16 batches. 8 threads per (b,j) pair split K=256.
// W_hh rows (j, 256+j, 512+j) live in registers. One global barrier per step.
__global__ void __launch_bounds__(256, 1) scan_kernel(const float* __restrict__ xg,
                                                      const float* __restrict__ Whh,
                                                      const float* __restrict__ bhh,
                                                      const float* __restrict__ h0) {
    int tid  = threadIdx.x;
    int pair = tid >> 3;          // 0..31
    int sub  = tid & 7;           // k-split lane
    int b    = pair & 15;
    int j    = blockIdx.x * 2 + (pair >> 4);   // 0..255

    // weights: k = sub*4 + i*32 + c  (contiguous float4 per 8-lane group)
    float w[3][8][4];
#pragma unroll
    for (int g = 0; g < 3; ++g) {
        const float* row = Whh + (size_t)(g * 256 + j) * 256;
#pragma unroll
        for (int i = 0; i < 8; ++i) {
            float4 v = *(const float4*)(row + i * 32 + sub * 4);
            w[g][i][0] = v.x; w[g][i][1] = v.y; w[g][i][2] = v.z; w[g][i][3] = v.w;
        }
    }
    float b_r = 0.f, b_z = 0.f, b_n = 0.f;
    if (sub == 0) { b_r = bhh[j]; b_z = bhh[256 + j]; b_n = bhh[512 + j]; }

    unsigned target = 0;
    for (int t = 0; t < 512; ++t) {
        const float* hread = (t == 0) ? (h0 + b * 256) : (&g_h[t & 1][b * 256]);
        float xr = 0.f, xz = 0.f, xn = 0.f, hold = 0.f;
        if (sub == 0) {
            const float* xrow = xg + (size_t)(b * 512 + t) * 768;
            xr = xrow[j]; xz = xrow[256 + j]; xn = xrow[512 + j];
            hold = hread[j];
        }
        float h[8][4];
#pragma unroll
        for (int i = 0; i < 8; ++i)
            *(float4*)h[i] = *(const float4*)(hread + i * 32 + sub * 4);
        float ar = 0.f, az = 0.f, an = 0.f;
#pragma unroll
        for (int i = 0; i < 8; ++i)
#pragma unroll
            for (int c = 0; c < 4; ++c) {
                ar = fmaf(w[0][i][c], h[i][c], ar);
                az = fmaf(w[1][i][c], h[i][c], az);
                an = fmaf(w[2][i][c], h[i][c], an);
            }
#pragma unroll
        for (int off = 4; off; off >>= 1) {
            ar += __shfl_down_sync(0xffffffffu, ar, off, 8);
            az += __shfl_down_sync(0xffffffffu, az, off, 8);
            an += __shfl_down_sync(0xffffffffu, an, off, 8);
        }
        if (sub == 0) {
            float r  = 1.f / (1.f + __expf(-(xr + ar + b_r)));
            float z  = 1.f / (1.f + __expf(-(xz + az + b_z)));
            float nn = tanhf(xn + r * (an + b_n));
            float hv = (1.f - z) * nn + z * hold;
            g_h[(t + 1) & 1][b * 256 + j] = hv;
            g_out[(size_t)(b * 512 + t) * 256 + j] = hv;
            __threadfence();
        }
        __syncthreads();
        if (tid == 0) red_release(&g_bar, 1u);
        target += NBQ;
        while (ld_acq(&g_bar) < target) { }
        __syncthreads();
    }
}

// ---------------- 9. attention logits: a = u @ W2^T + b2 ---------------------
__global__ void __launch_bounds__(256) logits_kernel(const float* __restrict__ W2,
                                                     const float* __restrict__ b2) {
    __shared__ float sW[8 * 256];
    for (int i = threadIdx.x; i < 2048; i += 256) sW[i] = W2[i];
    __syncthreads();
    int warp = threadIdx.x >> 5, lane = threadIdx.x & 31;
    int m = blockIdx.x * 8 + warp;           // row (b*T + t)
    const float* ur = g_u + (size_t)m * 256;
    float uv[8];
#pragma unroll
    for (int i = 0; i < 8; ++i) uv[i] = ur[i * 32 + lane];
#pragma unroll
    for (int hh = 0; hh < 8; ++hh) {
        float acc = 0.f;
#pragma unroll
        for (int i = 0; i < 8; ++i) acc = fmaf(uv[i], sW[hh * 256 + i * 32 + lane], acc);
#pragma unroll
        for (int off = 16; off; off >>= 1) acc += __shfl_down_sync(0xffffffffu, acc, off);
        if (lane == 0) g_a[(size_t)m * 8 + hh] = acc + b2[hh];
    }
}

// ---------------- 10. masked softmax over T; writes attention output ---------
__global__ void softmax_kernel(const int* __restrict__ lengths, float* __restrict__ att) {
    int bh = blockIdx.x, b = bh >> 3, hh = bh & 7;
    int t = threadIdx.x;                     // 512 threads
    int len = lengths[b];
    float v = (t < len) ? g_a[(size_t)(b * 512 + t) * 8 + hh] : -1e30f;
    __shared__ float red[16];
    __shared__ float bc[2];
    float m = v;
#pragma unroll
    for (int o = 16; o; o >>= 1) m = fmaxf(m, __shfl_xor_sync(0xffffffffu, m, o));
    if ((t & 31) == 0) red[t >> 5] = m;
    __syncthreads();
    if (t == 0) {
        float mm = red[0];
        for (int i = 1; i < 16; ++i) mm = fmaxf(mm, red[i]);
        bc[0] = mm;
    }
    __syncthreads();
    float e = __expf(v - bc[0]);
    float s = e;
#pragma unroll
    for (int o = 16; o; o >>= 1) s += __shfl_xor_sync(0xffffffffu, s, o);
    __syncthreads();
    if ((t & 31) == 0) red[t >> 5] = s;
    __syncthreads();
    if (t == 0) {
        float ss = 0.f;
        for (int i = 0; i < 16; ++i) ss += red[i];
        bc[1] = ss;
    }
    __syncthreads();
    att[(size_t)bh * 512 + t] = e / bc[1];
}

// ---------------- 11. sent/avg/final FC + hn copy ----------------------------
__global__ void __launch_bounds__(256) final_kernel(const float* __restrict__ att,
                                                    const float* __restrict__ Wf,
                                                    const float* __restrict__ bf,
                                                    float* __restrict__ out_main,
                                                    float* __restrict__ out_hn) {
    int b = blockIdx.x, d = threadIdx.x;
    __shared__ float sat[8][512];
    __shared__ float sav[256];
    for (int i = d; i < 4096; i += 256) sat[i >> 9][i & 511] = att[(size_t)b * 4096 + i];
    __syncthreads();
    const float* orow = g_out + (size_t)b * 512 * 256;
    float acc[8] = {0.f,0.f,0.f,0.f,0.f,0.f,0.f,0.f};
    for (int t = 0; t < 512; ++t) {
        float ov = orow[(size_t)t * 256 + d];
#pragma unroll
        for (int hh = 0; hh < 8; ++hh) acc[hh] = fmaf(sat[hh][t], ov, acc[hh]);
    }
    float avg = 0.f;
#pragma unroll
    for (int hh = 0; hh < 8; ++hh) avg += acc[hh];
    avg *= 0.125f;
    sav[d] = avg;
    out_hn[b * 256 + d] = orow[511 * 256 + d];
    __syncthreads();
    if (d < 10) {
        float s = bf[d];
        for (int k = 0; k < 256; ++k) s = fmaf(Wf[d * 256 + k], sav[k], s);
        out_main[b * 10 + d] = s;
    }
}

// ============================================================================
extern "C" void kernel_launch(void* const* d_in, const int* in_sizes, int n_in,
                              void* d_out, int out_size) {
    const int*   x      = (const int*)  d_in[0];
    const int*   len    = (const int*)  d_in[1];
    const float* h0     = (const float*)d_in[2];
    const float* emb    = (const float*)d_in[3];
    const float* G      = (const float*)d_in[4];
    const float* Gp     = (const float*)d_in[5];
    const float* mw     = (const float*)d_in[6];
    const float* Wc1    = (const float*)d_in[7];
    const float* Wc2    = (const float*)d_in[8];
    const float* W_ih   = (const float*)d_in[9];
    const float* W_hh   = (const float*)d_in[10];
    const float* b_ih   = (const float*)d_in[11];
    /* b_hh = d_in[12] used in scan */
    const float* b_hh   = (const float*)d_in[12];
    const float* W1     = (const float*)d_in[13];
    const float* b1     = (const float*)d_in[14];
    const float* W2     = (const float*)d_in[15];
    const float* b2     = (const float*)d_in[16];
    const float* Wf     = (const float*)d_in[17];
    const float* bf     = (const float*)d_in[18];

    float* out      = (float*)d_out;
    float* out_main = out;                 // (16,10)
    float* out_hn   = out + 160;           // (16,256)
    float* out_att  = out + 160 + 4096;    // (16,8,512)

    void *p;
    cudaGetSymbolAddress(&p, g_cat);  float* pcat  = (float*)p;
    cudaGetSymbolAddress(&p, g_c1);   float* pc1   = (float*)p;
    cudaGetSymbolAddress(&p, g_c2);   float* pc2   = (float*)p;
    cudaGetSymbolAddress(&p, g_next); float* pnext = (float*)p;
    cudaGetSymbolAddress(&p, g_xg);   float* pxg   = (float*)p;
    cudaGetSymbolAddress(&p, g_out);  float* pout  = (float*)p;
    cudaGetSymbolAddress(&p, g_u);    float* pu    = (float*)p;

    // 1. embedding gather (+ barrier reset)
    embed_kernel<<<8192, 64>>>(x, emb);
    // 2. adjacency mix
    mix_kernel<<<4096, 256>>>(G, Gp, mw);
    // 3. weighted = M^T @ Hemb  -> cat right half
    gemm_tn_kernel<<<dim3(8, 4, 16), 256>>>();
    // 4. GLU halves
    gemm_nt_kernel<<<dim3(128, 4), 256>>>(pcat, Wc1, pc1, 256, 512, nullptr, 0);
    gemm_nt_kernel<<<dim3(128, 4), 256>>>(pcat, Wc2, pc2, 256, 512, nullptr, 0);
    // 5. next_in = c1 * sigmoid(c2)
    glu_kernel<<<2048, 256>>>();
    // 6. xg = next_in @ W_ih^T + b_ih
    gemm_nt_kernel<<<dim3(128, 12), 256>>>(pnext, W_ih, pxg, 768, 256, b_ih, 1);
    // 7. GRU scan (persistent)
    scan_kernel<<<NBQ, 256>>>(pxg, W_hh, b_hh, h0);
    // 8. u = tanh(outputs @ W1^T + b1)
    gemm_nt_kernel<<<dim3(128, 4), 256>>>(pout, W1, pu, 256, 256, b1, 2);
    // 9. logits
    logits_kernel<<<1024, 256>>>(W2, b2);
    // 10. masked softmax -> attention output
    softmax_kernel<<<128, 512>>>(len, out_att);
    // 11. sent/avg/final + hn
    final_kernel<<<16, 256>>>(out_att, Wf, bf, out_main, out_hn);
}

// round 3
// speedup vs baseline: 1.5129x; 1.5129x over previous
#include <cuda_runtime.h>
#include <cstdint>

// B=16, T=512, E=256, H=256, HEADS=8, NL=3, NC=10

// ---------------- scratch (static device memory) -----------------------------
__device__ __align__(16) float g_M[16*512*512];     // mixed adjacency (B,T,T)
__device__ __align__(16) float g_cat[8192*512];     // [Hemb | weighted]
__device__ __align__(16) float g_c1[8192*256];
__device__ __align__(16) float g_next[8192*256];
__device__ __align__(16) float g_xg[8192*768];
__device__ __align__(16) float g_out[8192*256];
__device__ __align__(16) float g_u[8192*256];
__device__ __align__(16) float g_a[8192*8];
__device__ __align__(16) float g_sent[16*256];

// ---------------- helpers ----------------------------------------------------
__device__ __forceinline__ uint32_t smem_u32(const void* p) {
    uint32_t a;
    asm("{ .reg .u64 t; cvta.to.shared.u64 t, %1; cvt.u32.u64 %0, t; }"
        : "=r"(a) : "l"(p));
    return a;
}
__device__ __forceinline__ void dsmem_st(uint32_t laddr, int rank, float v) {
    uint32_t r;
    asm volatile("mapa.shared::cluster.u32 %0, %1, %2;" : "=r"(r) : "r"(laddr), "r"(rank));
    asm volatile("st.shared::cluster.f32 [%0], %1;" :: "r"(r), "f"(v) : "memory");
}
#define CLUSTER_SYNC_() do { \
    asm volatile("barrier.cluster.arrive.aligned;" ::: "memory"); \
    asm volatile("barrier.cluster.wait.aligned;"  ::: "memory"); } while (0)

// ---------------- 1. embedding gather ----------------------------------------
__global__ void embed_kernel(const int* __restrict__ x, const float* __restrict__ emb) {
    int m = blockIdx.x;                       // b*T + t
    int tok = x[m];
    float4 v = *(const float4*)(emb + (size_t)tok * 256 + threadIdx.x * 4);
    *(float4*)(g_cat + (size_t)m * 512 + threadIdx.x * 4) = v;
}

// ---------------- 2. M = sum_l w_l*G + (1-w_l)*G_prod ------------------------
__global__ void mix_kernel(const float* __restrict__ G, const float* __restrict__ Gp,
                           const float* __restrict__ mw) {
    int i = blockIdx.x * blockDim.x + threadIdx.x;   // over 16*65536 float4s
    float w0 = mw[0], w1 = mw[1], w2 = mw[2];
    int b = i >> 16;
    int r = i & 65535;
    const float4* G4  = (const float4*)G;
    const float4* Gp4 = (const float4*)Gp;
    size_t base = (size_t)b * 3 * 65536 + r;
    float4 g0 = G4[base],           p0 = Gp4[base];
    float4 g1 = G4[base + 65536],   p1 = Gp4[base + 65536];
    float4 g2 = G4[base + 131072],  p2 = Gp4[base + 131072];
    float4 o;
    o.x = w0*g0.x + (1.f-w0)*p0.x + w1*g1.x + (1.f-w1)*p1.x + w2*g2.x + (1.f-w2)*p2.x;
    o.y = w0*g0.y + (1.f-w0)*p0.y + w1*g1.y + (1.f-w1)*p1.y + w2*g2.y + (1.f-w2)*p2.y;
    o.z = w0*g0.z + (1.f-w0)*p0.z + w1*g1.z + (1.f-w1)*p1.z + w2*g2.z + (1.f-w2)*p2.z;
    o.w = w0*g0.w + (1.f-w0)*p0.w + w1*g1.w + (1.f-w1)*p1.w + w2*g2.w + (1.f-w2)*p2.w;
    ((float4*)g_M)[i] = o;
}

// ---------------- generic 128x64 GEMM ----------------------------------------
// TRANSA=1: A is K x M (k-major, direct copy).  TRANSA=0: A is M x K row-major.
// TRANSB=1: B is N x K row-major (NT).          TRANSB=0: B is K x N (NN).
// MODE: 0 plain, 1 +bias, 2 tanh(+bias), 3 GLU: C = aux * sigmoid(acc)
template<int TRANSA, int TRANSB, int MODE>
__global__ void __launch_bounds__(256) gemm128(
    const float* __restrict__ A, int lda,
    const float* __restrict__ B, int ldb,
    float* __restrict__ C, int ldc, int K,
    const float* __restrict__ bias, const float* __restrict__ aux,
    size_t sA, size_t sB, size_t sC)
{
    A += sA * blockIdx.z; B += sB * blockIdx.z; C += sC * blockIdx.z;
    if (MODE == 3) aux += sC * blockIdx.z;
    __shared__ __align__(16) float As[16][132];
    __shared__ __align__(16) float Bs[16][68];
    int tid = threadIdx.x;
    int m0b = blockIdx.x * 128, n0b = blockIdx.y * 64;
    int tm = tid >> 4, tn = tid & 15;

    float acc[8][4];
#pragma unroll
    for (int i = 0; i < 8; ++i)
#pragma unroll
        for (int j = 0; j < 4; ++j) acc[i][j] = 0.f;

    for (int k0 = 0; k0 < K; k0 += 16) {
        float4 a0, a1, b0;
        int akk = 0, amc = 0, ar = 0, akc = 0;
        if (TRANSA) {
            akk = tid >> 4; amc = (tid & 15) * 8;
            const float* src = A + (size_t)(k0 + akk) * lda + m0b + amc;
            a0 = *(const float4*)src;
            a1 = *(const float4*)(src + 4);
        } else {
            ar = tid >> 1; akc = (tid & 1) * 8;
            const float* src = A + (size_t)(m0b + ar) * lda + k0 + akc;
            a0 = *(const float4*)src;
            a1 = *(const float4*)(src + 4);
        }
        int bn = 0, bkc = 0, bkk = 0, bnc = 0;
        if (TRANSB) {
            bn = tid >> 2; bkc = (tid & 3) * 4;
            b0 = *(const float4*)(B + (size_t)(n0b + bn) * ldb + k0 + bkc);
        } else {
            bkk = tid >> 4; bnc = (tid & 15) * 4;
            b0 = *(const float4*)(B + (size_t)(k0 + bkk) * ldb + n0b + bnc);
        }
        __syncthreads();
        if (TRANSA) {
            *(float4*)&As[akk][amc]     = a0;
            *(float4*)&As[akk][amc + 4] = a1;
        } else {
            As[akc+0][ar] = a0.x; As[akc+1][ar] = a0.y;
            As[akc+2][ar] = a0.z; As[akc+3][ar] = a0.w;
            As[akc+4][ar] = a1.x; As[akc+5][ar] = a1.y;
            As[akc+6][ar] = a1.z; As[akc+7][ar] = a1.w;
        }
        if (TRANSB) {
            Bs[bkc+0][bn] = b0.x; Bs[bkc+1][bn] = b0.y;
            Bs[bkc+2][bn] = b0.z; Bs[bkc+3][bn] = b0.w;
        } else {
            *(float4*)&Bs[bkk][bnc] = b0;
        }
        __syncthreads();
#pragma unroll
        for (int kk = 0; kk < 16; ++kk) {
            float a8[8], b4[4];
            *(float4*)&a8[0] = *(const float4*)&As[kk][tm * 8];
            *(float4*)&a8[4] = *(const float4*)&As[kk][tm * 8 + 4];
            *(float4*)&b4[0] = *(const float4*)&Bs[kk][tn * 4];
#pragma unroll
            for (int i = 0; i < 8; ++i)
#pragma unroll
                for (int j = 0; j < 4; ++j)
                    acc[i][j] = fmaf(a8[i], b4[j], acc[i][j]);
        }
    }
    // epilogue
    float bias4[4] = {0.f, 0.f, 0.f, 0.f};
    if (MODE == 1 || MODE == 2) {
#pragma unroll
        for (int j = 0; j < 4; ++j) bias4[j] = bias[n0b + tn * 4 + j];
    }
#pragma unroll
    for (int i = 0; i < 8; ++i) {
        size_t row = (size_t)(m0b + tm * 8 + i) * ldc + n0b + tn * 4;
        float4 v;
        float vv[4];
#pragma unroll
        for (int j = 0; j < 4; ++j) {
            float t = acc[i][j];
            if (MODE == 1) t += bias4[j];
            if (MODE == 2) t = tanhf(t + bias4[j]);
            vv[j] = t;
        }
        if (MODE == 3) {
            float4 av = *(const float4*)(aux + row);
            vv[0] = av.x / (1.f + __expf(-vv[0]));
            vv[1] = av.y / (1.f + __expf(-vv[1]));
            vv[2] = av.z / (1.f + __expf(-vv[2]));
            vv[3] = av.w / (1.f + __expf(-vv[3]));
        }
        v.x = vv[0]; v.y = vv[1]; v.z = vv[2]; v.w = vv[3];
        *(float4*)(C + row) = v;
    }
}

// ---------------- GRU scan: 16 clusters x 8 CTAs, h in SMEM ------------------
// cluster = one batch. CTA rank r owns j in [r*32, r*32+32). 8 threads per j.
__global__ void __launch_bounds__(256, 1) __cluster_dims__(8, 1, 1)
scan_kernel(const float* __restrict__ xg, const float* __restrict__ Whh,
            const float* __restrict__ bhh, const float* __restrict__ h0)
{
    __shared__ __align__(16) float h[2][256];
    int tid  = threadIdx.x;
    int rank = blockIdx.x & 7;
    int b    = blockIdx.x >> 3;
    int pair = tid >> 3;          // 0..31
    int sub  = tid & 7;
    int j    = rank * 32 + pair;  // 0..255

    float4 w[3][8];
#pragma unroll
    for (int g = 0; g < 3; ++g) {
        const float* row = Whh + (size_t)(g * 256 + j) * 256;
#pragma unroll
        for (int i = 0; i < 8; ++i)
            w[g][i] = *(const float4*)(row + i * 32 + sub * 4);
    }
    float b_r = 0.f, b_z = 0.f, b_n = 0.f;
    if (sub == 0) { b_r = bhh[j]; b_z = bhh[256 + j]; b_n = bhh[512 + j]; }

    h[0][tid] = h0[b * 256 + tid];
    uint32_t hbase[2] = { smem_u32(&h[0][0]), smem_u32(&h[1][0]) };
    __syncthreads();
    CLUSTER_SYNC_();

    int p = 0;
    for (int t = 0; t < 512; ++t) {
        const float* xrow = xg + (size_t)(b * 512 + t) * 768;
        float xr = 0.f, xz = 0.f, xn = 0.f, hold = 0.f;
        if (sub == 0) {
            xr = xrow[j]; xz = xrow[256 + j]; xn = xrow[512 + j];
            hold = h[p][j];
        }
        float ar = 0.f, az = 0.f, an = 0.f;
#pragma unroll
        for (int i = 0; i < 8; ++i) {
            float4 hv = *(const float4*)&h[p][i * 32 + sub * 4];
            ar = fmaf(w[0][i].x, hv.x, ar); ar = fmaf(w[0][i].y, hv.y, ar);
            ar = fmaf(w[0][i].z, hv.z, ar); ar = fmaf(w[0][i].w, hv.w, ar);
            az = fmaf(w[1][i].x, hv.x, az); az = fmaf(w[1][i].y, hv.y, az);
            az = fmaf(w[1][i].z, hv.z, az); az = fmaf(w[1][i].w, hv.w, az);
            an = fmaf(w[2][i].x, hv.x, an); an = fmaf(w[2][i].y, hv.y, an);
            an = fmaf(w[2][i].z, hv.z, an); an = fmaf(w[2][i].w, hv.w, an);
        }
#pragma unroll
        for (int off = 4; off; off >>= 1) {
            ar += __shfl_down_sync(0xffffffffu, ar, off, 8);
            az += __shfl_down_sync(0xffffffffu, az, off, 8);
            an += __shfl_down_sync(0xffffffffu, an, off, 8);
        }
        if (sub == 0) {
            float r_ = 1.f / (1.f + __expf(-(xr + ar + b_r)));
            float z_ = 1.f / (1.f + __expf(-(xz + az + b_z)));
            float n_ = tanhf(xn + r_ * (an + b_n));
            float hv = (1.f - z_) * n_ + z_ * hold;
            g_out[(size_t)(b * 512 + t) * 256 + j] = hv;
            uint32_t laddr = hbase[p ^ 1] + (uint32_t)j * 4u;
#pragma unroll
            for (int rk = 0; rk < 8; ++rk) dsmem_st(laddr, rk, hv);
        }
        CLUSTER_SYNC_();
        p ^= 1;
    }
}

// ---------------- attention logits: a = u @ W2^T + b2 ------------------------
__global__ void __launch_bounds__(256) logits_kernel(const float* __restrict__ W2,
                                                     const float* __restrict__ b2) {
    __shared__ float sW[8 * 256];
    for (int i = threadIdx.x; i < 2048; i += 256) sW[i] = W2[i];
    __syncthreads();
    int warp = threadIdx.x >> 5, lane = threadIdx.x & 31;
    int m = blockIdx.x * 8 + warp;
    const float* ur = g_u + (size_t)m * 256;
    float uv[8];
#pragma unroll
    for (int i = 0; i < 8; ++i) uv[i] = ur[i * 32 + lane];
#pragma unroll
    for (int hh = 0; hh < 8; ++hh) {
        float acc = 0.f;
#pragma unroll
        for (int i = 0; i < 8; ++i) acc = fmaf(uv[i], sW[hh * 256 + i * 32 + lane], acc);
#pragma unroll
        for (int off = 16; off; off >>= 1) acc += __shfl_down_sync(0xffffffffu, acc, off);
        if (lane == 0) g_a[(size_t)m * 8 + hh] = acc + b2[hh];
    }
}

// ---------------- masked softmax over T --------------------------------------
__global__ void softmax_kernel(const int* __restrict__ lengths, float* __restrict__ att) {
    int bh = blockIdx.x, b = bh >> 3, hh = bh & 7;
    int t = threadIdx.x;
    int len = lengths[b];
    float v = (t < len) ? g_a[(size_t)(b * 512 + t) * 8 + hh] : -1e30f;
    __shared__ float red[16];
    __shared__ float bc[2];
    float m = v;
#pragma unroll
    for (int o = 16; o; o >>= 1) m = fmaxf(m, __shfl_xor_sync(0xffffffffu, m, o));
    if ((t & 31) == 0) red[t >> 5] = m;
    __syncthreads();
    if (t == 0) {
        float mm = red[0];
        for (int i = 1; i < 16; ++i) mm = fmaxf(mm, red[i]);
        bc[0] = mm;
    }
    __syncthreads();
    float e = __expf(v - bc[0]);
    float s = e;
#pragma unroll
    for (int o = 16; o; o >>= 1) s += __shfl_xor_sync(0xffffffffu, s, o);
    __syncthreads();
    if ((t & 31) == 0) red[t >> 5] = s;
    __syncthreads();
    if (t == 0) {
        float ss = 0.f;
        for (int i = 0; i < 16; ++i) ss += red[i];
        bc[1] = ss;
    }
    __syncthreads();
    att[(size_t)bh * 512 + t] = e / bc[1];
}

// ---------------- sent + avg (+hn copy) --------------------------------------
__global__ void __launch_bounds__(256) sent_kernel(const float* __restrict__ att,
                                                   float* __restrict__ out_hn) {
    int b = blockIdx.x, q = blockIdx.y;        // q -> 64-col slice
    __shared__ float sat[8][512];
    __shared__ float sred[4][8][64];
    int tid = threadIdx.x;
    for (int i = tid; i < 4096; i += 256) sat[i >> 9][i & 511] = att[(size_t)b * 4096 + i];
    __syncthreads();
    int dl = tid & 63, tc = tid >> 6;
    int d = q * 64 + dl;
    const float* orow = g_out + (size_t)b * 512 * 256;
    float acc[8] = {0.f,0.f,0.f,0.f,0.f,0.f,0.f,0.f};
    for (int t = tc * 128; t < tc * 128 + 128; ++t) {
        float ov = orow[(size_t)t * 256 + d];
#pragma unroll
        for (int hh = 0; hh < 8; ++hh) acc[hh] = fmaf(sat[hh][t], ov, acc[hh]);
    }
#pragma unroll
    for (int hh = 0; hh < 8; ++hh) sred[tc][hh][dl] = acc[hh];
    __syncthreads();
    if (tc == 0) {
        float s = 0.f;
#pragma unroll
        for (int hh = 0; hh < 8; ++hh)
            s += sred[0][hh][dl] + sred[1][hh][dl] + sred[2][hh][dl] + sred[3][hh][dl];
        g_sent[b * 256 + d] = s * 0.125f;
        out_hn[b * 256 + d] = orow[(size_t)511 * 256 + d];
    }
}

// ---------------- final FC ---------------------------------------------------
__global__ void fc_kernel(const float* __restrict__ Wf, const float* __restrict__ bf,
                          float* __restrict__ out_main) {
    int b = blockIdx.x;
    __shared__ float sv[256];
    sv[threadIdx.x] = g_sent[b * 256 + threadIdx.x];
    __syncthreads();
    if (threadIdx.x < 10) {
        float s = bf[threadIdx.x];
        for (int k = 0; k < 256; ++k) s = fmaf(Wf[threadIdx.x * 256 + k], sv[k], s);
        out_main[b * 10 + threadIdx.x] = s;
    }
}

// ============================================================================
extern "C" void kernel_launch(void* const* d_in, const int* in_sizes, int n_in,
                              void* d_out, int out_size) {
    const int*   x    = (const int*)  d_in[0];
    const int*   len  = (const int*)  d_in[1];
    const float* h0   = (const float*)d_in[2];
    const float* emb  = (const float*)d_in[3];
    const float* G    = (const float*)d_in[4];
    const float* Gp   = (const float*)d_in[5];
    const float* mw   = (const float*)d_in[6];
    const float* Wc1  = (const float*)d_in[7];
    const float* Wc2  = (const float*)d_in[8];
    const float* W_ih = (const float*)d_in[9];
    const float* W_hh = (const float*)d_in[10];
    const float* b_ih = (const float*)d_in[11];
    const float* b_hh = (const float*)d_in[12];
    const float* W1   = (const float*)d_in[13];
    const float* b1   = (const float*)d_in[14];
    const float* W2   = (const float*)d_in[15];
    const float* b2   = (const float*)d_in[16];
    const float* Wf   = (const float*)d_in[17];
    const float* bf   = (const float*)d_in[18];

    float* out      = (float*)d_out;
    float* out_main = out;
    float* out_hn   = out + 160;
    float* out_att  = out + 160 + 4096;

    void* p;
    cudaGetSymbolAddress(&p, g_M);    float* pM    = (float*)p;
    cudaGetSymbolAddress(&p, g_cat);  float* pcat  = (float*)p;
    cudaGetSymbolAddress(&p, g_c1);   float* pc1   = (float*)p;
    cudaGetSymbolAddress(&p, g_next); float* pnext = (float*)p;
    cudaGetSymbolAddress(&p, g_xg);   float* pxg   = (float*)p;
    cudaGetSymbolAddress(&p, g_out);  float* pout  = (float*)p;
    cudaGetSymbolAddress(&p, g_u);    float* pu    = (float*)p;

    // 1. embedding gather
    embed_kernel<<<8192, 64>>>(x, emb);
    // 2. adjacency mix
    mix_kernel<<<4096, 256>>>(G, Gp, mw);
    // 3. weighted = M^T @ Hemb (TN as k-major A, NN B) -> cat right half
    gemm128<1, 0, 0><<<dim3(4, 4, 16), 256>>>(
        pM, 512, pcat, 512, pcat + 256, 512, 512, nullptr, nullptr,
        (size_t)512 * 512, (size_t)512 * 512, (size_t)512 * 512);
    // 4. c1 = cat @ Wc1^T
    gemm128<0, 1, 0><<<dim3(64, 4), 256>>>(
        pcat, 512, Wc1, 512, pc1, 256, 512, nullptr, nullptr, 0, 0, 0);
    // 5. next = c1 * sigmoid(cat @ Wc2^T)   (GLU fused)
    gemm128<0, 1, 3><<<dim3(64, 4), 256>>>(
        pcat, 512, Wc2, 512, pnext, 256, 512, nullptr, pc1, 0, 0, 0);
    // 6. xg = next @ W_ih^T + b_ih
    gemm128<0, 1, 1><<<dim3(64, 12), 256>>>(
        pnext, 256, W_ih, 256, pxg, 768, 256, b_ih, nullptr, 0, 0, 0);
    // 7. GRU scan (cluster per batch)
    scan_kernel<<<128, 256>>>(pxg, W_hh, b_hh, h0);
    // 8. u = tanh(out @ W1^T + b1)
    gemm128<0, 1, 2><<<dim3(64, 4), 256>>>(
        pout, 256, W1, 256, pu, 256, 256, b1, nullptr, 0, 0, 0);
    // 9. logits
    logits_kernel<<<1024, 256>>>(W2, b2);
    // 10. masked softmax -> attention output
    softmax_kernel<<<128, 512>>>(len, out_att);
    // 11. sent + avg + hn
    sent_kernel<<<dim3(16, 4), 256>>>(out_att, out_hn);
    // 12. final FC
    fc_kernel<<<16, 256>>>(Wf, bf, out_main);
}